// round 1
// baseline (speedup 1.0000x reference)
#include <cuda_runtime.h>

#define NEG_SLOPE 0.2f
#define MAXN 100000
#define MAXE 3200000

static __device__ __forceinline__ float lrelu(float v) {
    return v > 0.f ? v : NEG_SLOPE * v;
}

static __device__ __forceinline__ void red_add(float* addr, float a) {
    asm volatile("red.global.add.f32 [%0], %1;" :: "l"(addr), "f"(a) : "memory");
}
static __device__ __forceinline__ void red_add_v2(float* addr, float a, float b) {
    asm volatile("red.global.add.v2.f32 [%0], {%1,%2};" :: "l"(addr), "f"(a), "f"(b) : "memory");
}
static __device__ __forceinline__ void red_add_v4(float* addr, float a, float b, float c, float d) {
    asm volatile("red.global.add.v4.f32 [%0], {%1,%2,%3,%4};"
                 :: "l"(addr), "f"(a), "f"(b), "f"(c), "f"(d) : "memory");
}

// ---------------- scratch (device globals; no runtime allocation) ----------------
__device__ int g_is64;
__device__ int g_src[MAXE];
__device__ int g_dst[MAXE];

__device__ __align__(16) float g_h1f[MAXN * 16];
__device__ __align__(16) float g_h1r[MAXN * 16];
__device__ float g_ssf[MAXN], g_sdf[MAXN], g_ssr[MAXN], g_sdr[MAXN];
__device__ __align__(16) float g_numf[MAXN * 16];
__device__ __align__(16) float g_numr[MAXN * 16];
__device__ float g_denf[MAXN], g_denr[MAXN];

__device__ float g_h2f[MAXN], g_h2r[MAXN];
__device__ float g_s2af[MAXN], g_s2bf[MAXN], g_s2ar[MAXN], g_s2br[MAXN];
__device__ float2 g_nd2f[MAXN], g_nd2r[MAXN];

// ---------------- dtype detection: int64 vs int32 edge_index ----------------
// If edge_index is int64 (values < 2^31), every odd int32 word among the first
// 256 words is a zero high-word. For genuine int32 data (uniform in [0,1e5)),
// 128 consecutive odd-position zeros has probability ~0.
__global__ void k_detect(const int* ei32, int twoE) {
    __shared__ int nz;
    if (threadIdx.x == 0) nz = 0;
    __syncthreads();
    int idx = 1 + 2 * (int)threadIdx.x;   // odd words 1..255
    if (idx < 2 * twoE && ei32[idx] != 0) atomicAdd(&nz, 1);
    __syncthreads();
    if (threadIdx.x == 0) g_is64 = (nz == 0) ? 1 : 0;
}

__global__ void k_convert(const void* ei, int E) {
    int j = blockIdx.x * blockDim.x + threadIdx.x;
    if (j >= E) return;
    if (g_is64) {
        const long long* p = (const long long*)ei;
        g_src[j] = (int)p[j];
        g_dst[j] = (int)p[E + j];
    } else {
        const int* p = (const int*)ei;
        g_src[j] = p[j];
        g_dst[j] = p[E + j];
    }
}

// ---------------- layer 1 node prep: h = x@W, attention scores, self-loop init ----------------
__global__ void k_node1(const float* __restrict__ x,
                        const float* __restrict__ W1,  const float* __restrict__ as1,
                        const float* __restrict__ ad1,
                        const float* __restrict__ W1r, const float* __restrict__ as1r,
                        const float* __restrict__ ad1r, int N) {
    int i = blockIdx.x * blockDim.x + threadIdx.x;
    if (i >= N) return;
    float x0 = x[3 * i], x1 = x[3 * i + 1], x2 = x[3 * i + 2];
    float hf[16], hr[16];
    float ssf = 0.f, sdf = 0.f, ssr = 0.f, sdr = 0.f;
#pragma unroll
    for (int f = 0; f < 16; f++) {
        float hv  = x0 * __ldg(&W1[f])  + x1 * __ldg(&W1[16 + f])  + x2 * __ldg(&W1[32 + f]);
        float hvr = x0 * __ldg(&W1r[f]) + x1 * __ldg(&W1r[16 + f]) + x2 * __ldg(&W1r[32 + f]);
        hf[f] = hv;  hr[f] = hvr;
        ssf += hv  * __ldg(&as1[f]);
        sdf += hv  * __ldg(&ad1[f]);
        ssr += hvr * __ldg(&as1r[f]);
        sdr += hvr * __ldg(&ad1r[f]);
    }
    g_ssf[i] = ssf; g_sdf[i] = sdf; g_ssr[i] = ssr; g_sdr[i] = sdr;
    // self-loop contribution (src == dst == i), no atomics needed
    float wf = __expf(lrelu(ssf + sdf));
    float wr = __expf(lrelu(ssr + sdr));
    g_denf[i] = wf;
    g_denr[i] = wr;
#pragma unroll
    for (int f = 0; f < 16; f++) {
        g_h1f[16 * i + f] = hf[f];
        g_h1r[16 * i + f] = hr[f];
        g_numf[16 * i + f] = wf * hf[f];
        g_numr[16 * i + f] = wr * hr[f];
    }
}

// ---------------- layer 1 edge pass: both directions fused ----------------
__global__ void k_edge1(int E) {
    int j = blockIdx.x * blockDim.x + threadIdx.x;
    if (j >= E) return;
    int s = g_src[j];
    int d = g_dst[j];
    // forward: edge s->d, accumulate into d
    float wf = __expf(lrelu(g_ssf[s] + g_sdf[d]));
    // reverse: edge d->s, accumulate into s
    float wr = __expf(lrelu(g_ssr[d] + g_sdr[s]));

    const float4* hf = (const float4*)&g_h1f[16 * s];
    const float4* hr = (const float4*)&g_h1r[16 * d];
    float* nf = &g_numf[16 * d];
    float* nr = &g_numr[16 * s];

    red_add(&g_denf[d], wf);
    red_add(&g_denr[s], wr);
#pragma unroll
    for (int q = 0; q < 4; q++) {
        float4 a = hf[q];
        red_add_v4(nf + 4 * q, wf * a.x, wf * a.y, wf * a.z, wf * a.w);
        float4 b = hr[q];
        red_add_v4(nr + 4 * q, wr * b.x, wr * b.y, wr * b.z, wr * b.w);
    }
}

// ---------------- layer 2 node prep: normalize, relu, x1@W2, scores, self-loop init ----------------
__global__ void k_node2(const float* __restrict__ b1,  const float* __restrict__ W2,
                        const float* __restrict__ as2, const float* __restrict__ ad2,
                        const float* __restrict__ b1r, const float* __restrict__ W2r,
                        const float* __restrict__ as2r, const float* __restrict__ ad2r, int N) {
    int i = blockIdx.x * blockDim.x + threadIdx.x;
    if (i >= N) return;
    float invf = 1.f / (g_denf[i] + 1e-16f);
    float invr = 1.f / (g_denr[i] + 1e-16f);
    float h2f = 0.f, h2r = 0.f;
#pragma unroll
    for (int f = 0; f < 16; f++) {
        float xf = fmaxf(g_numf[16 * i + f] * invf + __ldg(&b1[f]), 0.f);
        float xr = fmaxf(g_numr[16 * i + f] * invr + __ldg(&b1r[f]), 0.f);
        h2f += xf * __ldg(&W2[f]);
        h2r += xr * __ldg(&W2r[f]);
    }
    float s2af = h2f * __ldg(&as2[0]),  s2bf = h2f * __ldg(&ad2[0]);
    float s2ar = h2r * __ldg(&as2r[0]), s2br = h2r * __ldg(&ad2r[0]);
    g_h2f[i] = h2f;  g_h2r[i] = h2r;
    g_s2af[i] = s2af; g_s2bf[i] = s2bf;
    g_s2ar[i] = s2ar; g_s2br[i] = s2br;
    float wf = __expf(lrelu(s2af + s2bf));
    float wr = __expf(lrelu(s2ar + s2br));
    g_nd2f[i] = make_float2(wf * h2f, wf);
    g_nd2r[i] = make_float2(wr * h2r, wr);
}

// ---------------- layer 2 edge pass: both directions fused ----------------
__global__ void k_edge2(int E) {
    int j = blockIdx.x * blockDim.x + threadIdx.x;
    if (j >= E) return;
    int s = g_src[j];
    int d = g_dst[j];
    float wf = __expf(lrelu(g_s2af[s] + g_s2bf[d]));
    float wr = __expf(lrelu(g_s2ar[d] + g_s2br[s]));
    red_add_v2((float*)&g_nd2f[d], wf * g_h2f[s], wf);
    red_add_v2((float*)&g_nd2r[s], wr * g_h2r[d], wr);
}

// ---------------- final combine ----------------
__global__ void k_out(float* __restrict__ out, const float* __restrict__ b2,
                      const float* __restrict__ b2r, int N) {
    int i = blockIdx.x * blockDim.x + threadIdx.x;
    if (i >= N) return;
    float2 f = g_nd2f[i];
    float2 r = g_nd2r[i];
    float of = f.x / (f.y + 1e-16f) + __ldg(&b2[0]);
    float orv = r.x / (r.y + 1e-16f) + __ldg(&b2r[0]);
    out[i] = 0.5f * (of + orv);
}

extern "C" void kernel_launch(void* const* d_in, const int* in_sizes, int n_in,
                              void* d_out, int out_size) {
    const float* x   = (const float*)d_in[0];
    const void*  ei  = d_in[1];
    const float* W1  = (const float*)d_in[2];
    const float* as1 = (const float*)d_in[3];
    const float* ad1 = (const float*)d_in[4];
    const float* b1  = (const float*)d_in[5];
    const float* W2  = (const float*)d_in[6];
    const float* as2 = (const float*)d_in[7];
    const float* ad2 = (const float*)d_in[8];
    const float* b2  = (const float*)d_in[9];
    const float* W1r  = (const float*)d_in[10];
    const float* as1r = (const float*)d_in[11];
    const float* ad1r = (const float*)d_in[12];
    const float* b1r  = (const float*)d_in[13];
    const float* W2r  = (const float*)d_in[14];
    const float* as2r = (const float*)d_in[15];
    const float* ad2r = (const float*)d_in[16];
    const float* b2r  = (const float*)d_in[17];

    int N = in_sizes[0] / 3;
    int E = in_sizes[1] / 2;

    const int TB = 256;
    int nbN = (N + TB - 1) / TB;
    int nbE = (E + TB - 1) / TB;

    k_detect<<<1, 128>>>((const int*)ei, 2 * E);
    k_convert<<<nbE, TB>>>(ei, E);
    k_node1<<<nbN, TB>>>(x, W1, as1, ad1, W1r, as1r, ad1r, N);
    k_edge1<<<nbE, TB>>>(E);
    k_node2<<<nbN, TB>>>(b1, W2, as2, ad2, b1r, W2r, as2r, ad2r, N);
    k_edge2<<<nbE, TB>>>(E);
    k_out<<<nbN, TB>>>((float*)d_out, b2, b2r, N);
}

// round 2
// speedup vs baseline: 2.7120x; 2.7120x over previous
#include <cuda_runtime.h>

#define NEG_SLOPE 0.2f
#define MAXN 100000
#define MAXE 3200000

static __device__ __forceinline__ float lrelu(float v) {
    return v > 0.f ? v : NEG_SLOPE * v;
}

static __device__ __forceinline__ void red_add_v2(float* addr, float a, float b) {
    asm volatile("red.global.add.v2.f32 [%0], {%1,%2};" :: "l"(addr), "f"(a), "f"(b) : "memory");
}
static __device__ __forceinline__ void red_add_v4(float* addr, float a, float b, float c, float d) {
    asm volatile("red.global.add.v4.f32 [%0], {%1,%2,%3,%4};"
                 :: "l"(addr), "f"(a), "f"(b), "f"(c), "f"(d) : "memory");
}

// ---------------- scratch (device globals; no runtime allocation) ----------------
__device__ int g_is64;
__device__ int g_src[MAXE];
__device__ int g_dst[MAXE];

// Layer-1 per-node pack: U[2i] = (x0,x1,x2, ssf), U[2i+1] = (sdf, ssr, sdr, 0)
// 32B-aligned so one node's pack = one L2 sector.
__device__ __align__(32) float4 g_U[MAXN * 2];
// Accumulators: (sum w*x0, w*x1, w*x2, sum w)  -- den folded into .w
__device__ float4 g_accf[MAXN];
__device__ float4 g_accr[MAXN];

// Layer-2 per-node pack: V[2i] = (s2af, s2bf, s2ar, s2br), V[2i+1] = (h2f, h2r, 0, 0)
__device__ __align__(32) float4 g_V[MAXN * 2];
__device__ __align__(16) float2 g_nd2f[MAXN];
__device__ __align__(16) float2 g_nd2r[MAXN];

// ---------------- dtype detection: int64 vs int32 edge_index ----------------
__global__ void k_detect(const int* ei32, int twoE) {
    __shared__ int nz;
    if (threadIdx.x == 0) nz = 0;
    __syncthreads();
    int idx = 1 + 2 * (int)threadIdx.x;   // odd words 1..255
    if (idx < 2 * twoE && ei32[idx] != 0) atomicAdd(&nz, 1);
    __syncthreads();
    if (threadIdx.x == 0) g_is64 = (nz == 0) ? 1 : 0;
}

__global__ void k_convert(const void* ei, int E) {
    int j = blockIdx.x * blockDim.x + threadIdx.x;
    if (j >= E) return;
    if (g_is64) {
        const long long* p = (const long long*)ei;
        g_src[j] = (int)p[j];
        g_dst[j] = (int)p[E + j];
    } else {
        const int* p = (const int*)ei;
        g_src[j] = p[j];
        g_dst[j] = p[E + j];
    }
}

// ---------------- layer 1 node prep ----------------
// scores: ssf[i] = x[i] . (W1 @ as1), etc. Self-loop contribution initialized
// directly into the accumulators (w*x, w).
__global__ void k_node1(const float* __restrict__ x,
                        const float* __restrict__ W1,  const float* __restrict__ as1,
                        const float* __restrict__ ad1,
                        const float* __restrict__ W1r, const float* __restrict__ as1r,
                        const float* __restrict__ ad1r, int N) {
    int i = blockIdx.x * blockDim.x + threadIdx.x;
    if (i >= N) return;
    float x0 = x[3 * i], x1 = x[3 * i + 1], x2 = x[3 * i + 2];

    float csf[3] = {0.f, 0.f, 0.f}, cdf[3] = {0.f, 0.f, 0.f};
    float csr[3] = {0.f, 0.f, 0.f}, cdr[3] = {0.f, 0.f, 0.f};
#pragma unroll
    for (int f = 0; f < 16; f++) {
        float a1 = __ldg(&as1[f]),  a2 = __ldg(&ad1[f]);
        float a3 = __ldg(&as1r[f]), a4 = __ldg(&ad1r[f]);
#pragma unroll
        for (int k = 0; k < 3; k++) {
            float w  = __ldg(&W1[16 * k + f]);
            float wr = __ldg(&W1r[16 * k + f]);
            csf[k] += w * a1;  cdf[k] += w * a2;
            csr[k] += wr * a3; cdr[k] += wr * a4;
        }
    }
    float ssf = x0 * csf[0] + x1 * csf[1] + x2 * csf[2];
    float sdf = x0 * cdf[0] + x1 * cdf[1] + x2 * cdf[2];
    float ssr = x0 * csr[0] + x1 * csr[1] + x2 * csr[2];
    float sdr = x0 * cdr[0] + x1 * cdr[1] + x2 * cdr[2];

    g_U[2 * i]     = make_float4(x0, x1, x2, ssf);
    g_U[2 * i + 1] = make_float4(sdf, ssr, sdr, 0.f);

    float wf = __expf(lrelu(ssf + sdf));
    float wr = __expf(lrelu(ssr + sdr));
    g_accf[i] = make_float4(wf * x0, wf * x1, wf * x2, wf);
    g_accr[i] = make_float4(wr * x0, wr * x1, wr * x2, wr);
}

// ---------------- layer 1 edge pass: both directions, 4 random sectors/edge ----------------
__global__ void k_edge1(int E) {
    int j = blockIdx.x * blockDim.x + threadIdx.x;
    if (j >= E) return;
    int s = g_src[j];
    int d = g_dst[j];

    float4 As = g_U[2 * s];                                   // x[s], ssf[s]
    float  sdr_s = ((const float*)&g_U[2 * s + 1])[2];        // sdr[s] (same sector)
    float4 Ad = g_U[2 * d];                                   // x[d], ssf[d] (unused .w)
    float2 Bd = *(const float2*)&g_U[2 * d + 1];              // sdf[d], ssr[d] (same sector)

    // forward edge s->d
    float wf = __expf(lrelu(As.w + Bd.x));
    // reverse edge d->s
    float wr = __expf(lrelu(Bd.y + sdr_s));

    red_add_v4((float*)&g_accf[d], wf * As.x, wf * As.y, wf * As.z, wf);
    red_add_v4((float*)&g_accr[s], wr * Ad.x, wr * Ad.y, wr * Ad.z, wr);
}

// ---------------- layer 2 node prep ----------------
// num_f = (sum w*x) @ W1  (linearity), x1 = relu(num_f/den + b1), h2 = x1 @ W2
__global__ void k_node2(const float* __restrict__ W1, const float* __restrict__ b1,
                        const float* __restrict__ W2,
                        const float* __restrict__ as2, const float* __restrict__ ad2,
                        const float* __restrict__ W1r, const float* __restrict__ b1r,
                        const float* __restrict__ W2r,
                        const float* __restrict__ as2r, const float* __restrict__ ad2r, int N) {
    int i = blockIdx.x * blockDim.x + threadIdx.x;
    if (i >= N) return;
    float4 af = g_accf[i];
    float4 ar = g_accr[i];
    float invf = 1.f / (af.w + 1e-16f);
    float invr = 1.f / (ar.w + 1e-16f);
    float n0f = af.x * invf, n1f = af.y * invf, n2f = af.z * invf;
    float n0r = ar.x * invr, n1r = ar.y * invr, n2r = ar.z * invr;

    float h2f = 0.f, h2r = 0.f;
#pragma unroll
    for (int f = 0; f < 16; f++) {
        float vf = n0f * __ldg(&W1[f]) + n1f * __ldg(&W1[16 + f]) + n2f * __ldg(&W1[32 + f])
                 + __ldg(&b1[f]);
        float vr = n0r * __ldg(&W1r[f]) + n1r * __ldg(&W1r[16 + f]) + n2r * __ldg(&W1r[32 + f])
                 + __ldg(&b1r[f]);
        h2f += fmaxf(vf, 0.f) * __ldg(&W2[f]);
        h2r += fmaxf(vr, 0.f) * __ldg(&W2r[f]);
    }
    float s2af = h2f * __ldg(&as2[0]),  s2bf = h2f * __ldg(&ad2[0]);
    float s2ar = h2r * __ldg(&as2r[0]), s2br = h2r * __ldg(&ad2r[0]);

    g_V[2 * i]     = make_float4(s2af, s2bf, s2ar, s2br);
    g_V[2 * i + 1] = make_float4(h2f, h2r, 0.f, 0.f);

    float wf = __expf(lrelu(s2af + s2bf));
    float wr = __expf(lrelu(s2ar + s2br));
    g_nd2f[i] = make_float2(wf * h2f, wf);
    g_nd2r[i] = make_float2(wr * h2r, wr);
}

// ---------------- layer 2 edge pass: 4 random sectors/edge ----------------
__global__ void k_edge2(int E) {
    int j = blockIdx.x * blockDim.x + threadIdx.x;
    if (j >= E) return;
    int s = g_src[j];
    int d = g_dst[j];

    float4 Vs = g_V[2 * s];                                   // scores pack, index s
    float  h2f_s = ((const float*)&g_V[2 * s + 1])[0];        // h2f[s] (same sector)
    float4 Vd = g_V[2 * d];
    float  h2r_d = ((const float*)&g_V[2 * d + 1])[1];        // h2r[d] (same sector)

    float wf = __expf(lrelu(Vs.x + Vd.y));   // s2af[s] + s2bf[d]
    float wr = __expf(lrelu(Vd.z + Vs.w));   // s2ar[d] + s2br[s]

    red_add_v2((float*)&g_nd2f[d], wf * h2f_s, wf);
    red_add_v2((float*)&g_nd2r[s], wr * h2r_d, wr);
}

// ---------------- final combine ----------------
__global__ void k_out(float* __restrict__ out, const float* __restrict__ b2,
                      const float* __restrict__ b2r, int N) {
    int i = blockIdx.x * blockDim.x + threadIdx.x;
    if (i >= N) return;
    float2 f = g_nd2f[i];
    float2 r = g_nd2r[i];
    float of  = f.x / (f.y + 1e-16f) + __ldg(&b2[0]);
    float orv = r.x / (r.y + 1e-16f) + __ldg(&b2r[0]);
    out[i] = 0.5f * (of + orv);
}

extern "C" void kernel_launch(void* const* d_in, const int* in_sizes, int n_in,
                              void* d_out, int out_size) {
    const float* x   = (const float*)d_in[0];
    const void*  ei  = d_in[1];
    const float* W1  = (const float*)d_in[2];
    const float* as1 = (const float*)d_in[3];
    const float* ad1 = (const float*)d_in[4];
    const float* b1  = (const float*)d_in[5];
    const float* W2  = (const float*)d_in[6];
    const float* as2 = (const float*)d_in[7];
    const float* ad2 = (const float*)d_in[8];
    const float* b2  = (const float*)d_in[9];
    const float* W1r  = (const float*)d_in[10];
    const float* as1r = (const float*)d_in[11];
    const float* ad1r = (const float*)d_in[12];
    const float* b1r  = (const float*)d_in[13];
    const float* W2r  = (const float*)d_in[14];
    const float* as2r = (const float*)d_in[15];
    const float* ad2r = (const float*)d_in[16];
    const float* b2r  = (const float*)d_in[17];

    int N = in_sizes[0] / 3;
    int E = in_sizes[1] / 2;

    const int TB = 256;
    int nbN = (N + TB - 1) / TB;
    int nbE = (E + TB - 1) / TB;

    k_detect<<<1, 128>>>((const int*)ei, 2 * E);
    k_convert<<<nbE, TB>>>(ei, E);
    k_node1<<<nbN, TB>>>(x, W1, as1, ad1, W1r, as1r, ad1r, N);
    k_edge1<<<nbE, TB>>>(E);
    k_node2<<<nbN, TB>>>(W1, b1, W2, as2, ad2, W1r, b1r, W2r, as2r, ad2r, N);
    k_edge2<<<nbE, TB>>>(E);
    k_out<<<nbN, TB>>>((float*)d_out, b2, b2r, N);
}

// round 3
// speedup vs baseline: 2.7365x; 1.0091x over previous
#include <cuda_runtime.h>

#define NEG_SLOPE 0.2f
#define MAXN 100000
#define MAXE 3200000
#define EPT 4          // edges per thread in edge passes

static __device__ __forceinline__ float lrelu(float v) {
    return v > 0.f ? v : NEG_SLOPE * v;
}

static __device__ __forceinline__ void red_add_v2(float* addr, float a, float b) {
    asm volatile("red.global.add.v2.f32 [%0], {%1,%2};" :: "l"(addr), "f"(a), "f"(b) : "memory");
}
static __device__ __forceinline__ void red_add_v4(float* addr, float a, float b, float c, float d) {
    asm volatile("red.global.add.v4.f32 [%0], {%1,%2,%3,%4};"
                 :: "l"(addr), "f"(a), "f"(b), "f"(c), "f"(d) : "memory");
}

// ---------------- scratch (device globals; no runtime allocation) ----------------
__device__ int g_is64;
__device__ __align__(16) int2 g_sd[MAXE];   // packed (src,dst), written by edge1, read by edge2

// Layer-1 per-node pack: U[2i] = (x0,x1,x2, ssf), U[2i+1] = (sdf, ssr, sdr, 0)
// 32B-aligned: one node's pack = one L2 sector.
__device__ __align__(32) float4 g_U[MAXN * 2];
// Accumulators: (sum w*x0, w*x1, w*x2, sum w)
__device__ __align__(16) float4 g_accf[MAXN];
__device__ __align__(16) float4 g_accr[MAXN];

// Layer-2 per-node pack: V[2i] = (s2af, s2bf, s2ar, s2br), V[2i+1] = (h2f, h2r, 0, 0)
__device__ __align__(32) float4 g_V[MAXN * 2];
__device__ __align__(16) float2 g_nd2f[MAXN];
__device__ __align__(16) float2 g_nd2r[MAXN];

// ---------------- dtype detection: int64 vs int32 edge_index ----------------
__global__ void k_detect(const int* ei32, int twoE) {
    __shared__ int nz;
    if (threadIdx.x == 0) nz = 0;
    __syncthreads();
    int idx = 1 + 2 * (int)threadIdx.x;   // odd words 1..255
    if (idx < 2 * twoE && ei32[idx] != 0) atomicAdd(&nz, 1);
    __syncthreads();
    if (threadIdx.x == 0) g_is64 = (nz == 0) ? 1 : 0;
}

// ---------------- layer 1 node prep ----------------
__global__ void k_node1(const float* __restrict__ x,
                        const float* __restrict__ W1,  const float* __restrict__ as1,
                        const float* __restrict__ ad1,
                        const float* __restrict__ W1r, const float* __restrict__ as1r,
                        const float* __restrict__ ad1r, int N) {
    int i = blockIdx.x * blockDim.x + threadIdx.x;
    if (i >= N) return;
    float x0 = x[3 * i], x1 = x[3 * i + 1], x2 = x[3 * i + 2];

    float csf[3] = {0.f, 0.f, 0.f}, cdf[3] = {0.f, 0.f, 0.f};
    float csr[3] = {0.f, 0.f, 0.f}, cdr[3] = {0.f, 0.f, 0.f};
#pragma unroll
    for (int f = 0; f < 16; f++) {
        float a1 = __ldg(&as1[f]),  a2 = __ldg(&ad1[f]);
        float a3 = __ldg(&as1r[f]), a4 = __ldg(&ad1r[f]);
#pragma unroll
        for (int k = 0; k < 3; k++) {
            float w  = __ldg(&W1[16 * k + f]);
            float wr = __ldg(&W1r[16 * k + f]);
            csf[k] += w * a1;  cdf[k] += w * a2;
            csr[k] += wr * a3; cdr[k] += wr * a4;
        }
    }
    float ssf = x0 * csf[0] + x1 * csf[1] + x2 * csf[2];
    float sdf = x0 * cdf[0] + x1 * cdf[1] + x2 * cdf[2];
    float ssr = x0 * csr[0] + x1 * csr[1] + x2 * csr[2];
    float sdr = x0 * cdr[0] + x1 * cdr[1] + x2 * cdr[2];

    g_U[2 * i]     = make_float4(x0, x1, x2, ssf);
    g_U[2 * i + 1] = make_float4(sdf, ssr, sdr, 0.f);

    float wf = __expf(lrelu(ssf + sdf));
    float wr = __expf(lrelu(ssr + sdr));
    g_accf[i] = make_float4(wf * x0, wf * x1, wf * x2, wf);
    g_accr[i] = make_float4(wr * x0, wr * x1, wr * x2, wr);
}

// ---------------- layer 1 edge pass: 4 edges/thread, fused index conversion ----------------
__global__ void __launch_bounds__(256) k_edge1(const void* __restrict__ ei, int E) {
    int t = blockIdx.x * blockDim.x + threadIdx.x;
    int j0 = t * EPT;
    if (j0 >= E) return;
    int n = E - j0; if (n > EPT) n = EPT;

    int s[EPT], d[EPT];
    if (g_is64) {
        const long long* p = (const long long*)ei;
#pragma unroll
        for (int u = 0; u < EPT; u++) if (u < n) { s[u] = (int)p[j0 + u]; d[u] = (int)p[E + j0 + u]; }
    } else {
        const int* p = (const int*)ei;
#pragma unroll
        for (int u = 0; u < EPT; u++) if (u < n) { s[u] = p[j0 + u]; d[u] = p[E + j0 + u]; }
    }
#pragma unroll
    for (int u = 0; u < EPT; u++) if (u < n) g_sd[j0 + u] = make_int2(s[u], d[u]);

    float4 As[EPT], Ad[EPT];
    float2 Bd[EPT];
    float  sdr_s[EPT];
#pragma unroll
    for (int u = 0; u < EPT; u++) if (u < n) {
        As[u]    = g_U[2 * s[u]];                               // x[s], ssf[s]
        sdr_s[u] = ((const float*)&g_U[2 * s[u] + 1])[2];       // sdr[s] (same sector)
        Ad[u]    = g_U[2 * d[u]];                               // x[d]
        Bd[u]    = *(const float2*)&g_U[2 * d[u] + 1];          // sdf[d], ssr[d] (same sector)
    }
#pragma unroll
    for (int u = 0; u < EPT; u++) if (u < n) {
        float wf = __expf(lrelu(As[u].w + Bd[u].x));            // forward s->d
        float wr = __expf(lrelu(Bd[u].y + sdr_s[u]));           // reverse d->s
        red_add_v4((float*)&g_accf[d[u]], wf * As[u].x, wf * As[u].y, wf * As[u].z, wf);
        red_add_v4((float*)&g_accr[s[u]], wr * Ad[u].x, wr * Ad[u].y, wr * Ad[u].z, wr);
    }
}

// ---------------- layer 2 node prep ----------------
__global__ void k_node2(const float* __restrict__ W1, const float* __restrict__ b1,
                        const float* __restrict__ W2,
                        const float* __restrict__ as2, const float* __restrict__ ad2,
                        const float* __restrict__ W1r, const float* __restrict__ b1r,
                        const float* __restrict__ W2r,
                        const float* __restrict__ as2r, const float* __restrict__ ad2r, int N) {
    int i = blockIdx.x * blockDim.x + threadIdx.x;
    if (i >= N) return;
    float4 af = g_accf[i];
    float4 ar = g_accr[i];
    float invf = 1.f / (af.w + 1e-16f);
    float invr = 1.f / (ar.w + 1e-16f);
    float n0f = af.x * invf, n1f = af.y * invf, n2f = af.z * invf;
    float n0r = ar.x * invr, n1r = ar.y * invr, n2r = ar.z * invr;

    float h2f = 0.f, h2r = 0.f;
#pragma unroll
    for (int f = 0; f < 16; f++) {
        float vf = n0f * __ldg(&W1[f]) + n1f * __ldg(&W1[16 + f]) + n2f * __ldg(&W1[32 + f])
                 + __ldg(&b1[f]);
        float vr = n0r * __ldg(&W1r[f]) + n1r * __ldg(&W1r[16 + f]) + n2r * __ldg(&W1r[32 + f])
                 + __ldg(&b1r[f]);
        h2f += fmaxf(vf, 0.f) * __ldg(&W2[f]);
        h2r += fmaxf(vr, 0.f) * __ldg(&W2r[f]);
    }
    float s2af = h2f * __ldg(&as2[0]),  s2bf = h2f * __ldg(&ad2[0]);
    float s2ar = h2r * __ldg(&as2r[0]), s2br = h2r * __ldg(&ad2r[0]);

    g_V[2 * i]     = make_float4(s2af, s2bf, s2ar, s2br);
    g_V[2 * i + 1] = make_float4(h2f, h2r, 0.f, 0.f);

    float wf = __expf(lrelu(s2af + s2bf));
    float wr = __expf(lrelu(s2ar + s2br));
    g_nd2f[i] = make_float2(wf * h2f, wf);
    g_nd2r[i] = make_float2(wr * h2r, wr);
}

// ---------------- layer 2 edge pass: 4 edges/thread ----------------
__global__ void __launch_bounds__(256) k_edge2(int E) {
    int t = blockIdx.x * blockDim.x + threadIdx.x;
    int j0 = t * EPT;
    if (j0 >= E) return;
    int n = E - j0; if (n > EPT) n = EPT;

    int2 sd[EPT];
#pragma unroll
    for (int u = 0; u < EPT; u++) if (u < n) sd[u] = g_sd[j0 + u];

    float4 Vs[EPT], Vd[EPT];
    float  hfs[EPT], hrd[EPT];
#pragma unroll
    for (int u = 0; u < EPT; u++) if (u < n) {
        Vs[u]  = g_V[2 * sd[u].x];
        hfs[u] = ((const float*)&g_V[2 * sd[u].x + 1])[0];      // h2f[s] (same sector)
        Vd[u]  = g_V[2 * sd[u].y];
        hrd[u] = ((const float*)&g_V[2 * sd[u].y + 1])[1];      // h2r[d] (same sector)
    }
#pragma unroll
    for (int u = 0; u < EPT; u++) if (u < n) {
        float wf = __expf(lrelu(Vs[u].x + Vd[u].y));            // s2af[s] + s2bf[d]
        float wr = __expf(lrelu(Vd[u].z + Vs[u].w));            // s2ar[d] + s2br[s]
        red_add_v2((float*)&g_nd2f[sd[u].y], wf * hfs[u], wf);
        red_add_v2((float*)&g_nd2r[sd[u].x], wr * hrd[u], wr);
    }
}

// ---------------- final combine ----------------
__global__ void k_out(float* __restrict__ out, const float* __restrict__ b2,
                      const float* __restrict__ b2r, int N) {
    int i = blockIdx.x * blockDim.x + threadIdx.x;
    if (i >= N) return;
    float2 f = g_nd2f[i];
    float2 r = g_nd2r[i];
    float of  = f.x / (f.y + 1e-16f) + __ldg(&b2[0]);
    float orv = r.x / (r.y + 1e-16f) + __ldg(&b2r[0]);
    out[i] = 0.5f * (of + orv);
}

extern "C" void kernel_launch(void* const* d_in, const int* in_sizes, int n_in,
                              void* d_out, int out_size) {
    const float* x   = (const float*)d_in[0];
    const void*  ei  = d_in[1];
    const float* W1  = (const float*)d_in[2];
    const float* as1 = (const float*)d_in[3];
    const float* ad1 = (const float*)d_in[4];
    const float* b1  = (const float*)d_in[5];
    const float* W2  = (const float*)d_in[6];
    const float* as2 = (const float*)d_in[7];
    const float* ad2 = (const float*)d_in[8];
    const float* b2  = (const float*)d_in[9];
    const float* W1r  = (const float*)d_in[10];
    const float* as1r = (const float*)d_in[11];
    const float* ad1r = (const float*)d_in[12];
    const float* b1r  = (const float*)d_in[13];
    const float* W2r  = (const float*)d_in[14];
    const float* as2r = (const float*)d_in[15];
    const float* ad2r = (const float*)d_in[16];
    const float* b2r  = (const float*)d_in[17];

    int N = in_sizes[0] / 3;
    int E = in_sizes[1] / 2;

    const int TB = 256;
    int nbN = (N + TB - 1) / TB;
    int nbE = (E + TB * EPT - 1) / (TB * EPT);

    k_detect<<<1, 128>>>((const int*)ei, 2 * E);
    k_node1<<<nbN, TB>>>(x, W1, as1, ad1, W1r, as1r, ad1r, N);
    k_edge1<<<nbE, TB>>>(ei, E);
    k_node2<<<nbN, TB>>>(W1, b1, W2, as2, ad2, W1r, b1r, W2r, as2r, ad2r, N);
    k_edge2<<<nbE, TB>>>(E);
    k_out<<<nbN, TB>>>((float*)d_out, b2, b2r, N);
}

// round 4
// speedup vs baseline: 2.9497x; 1.0779x over previous
#include <cuda_runtime.h>

#define NEG_SLOPE 0.2f
#define MAXN 100000
#define MAXE 3200000
#define EPT 4          // edges per thread in edge passes

static __device__ __forceinline__ float lrelu(float v) {
    return v > 0.f ? v : NEG_SLOPE * v;
}

static __device__ __forceinline__ void red_add_v2(float* addr, float a, float b) {
    asm volatile("red.global.add.v2.f32 [%0], {%1,%2};" :: "l"(addr), "f"(a), "f"(b) : "memory");
}
static __device__ __forceinline__ void red_add_v4(float* addr, float a, float b, float c, float d) {
    asm volatile("red.global.add.v4.f32 [%0], {%1,%2,%3,%4};"
                 :: "l"(addr), "f"(a), "f"(b), "f"(c), "f"(d) : "memory");
}

static __device__ __forceinline__ float dot3(float4 v, float4 c) {
    return v.x * c.x + v.y * c.y + v.z * c.z;
}

// ---------------- scratch (device globals; no runtime allocation) ----------------
__device__ __align__(16) int2 g_sd[MAXE];    // packed (src,dst): written by edge1, read by edge2

// Layer-1: per-node state is just x (float4-aligned, 1 sector). Scores are
// linear in x: score = x . coeff, coeffs are uniform (computed in node1).
__device__ __align__(16) float4 g_X[MAXN];
__device__ float4 g_csf, g_cdf, g_csr, g_cdr;   // W1@as1, W1@ad1, W1r@as1r, W1r@ad1r
// Accumulators: (sum w*x0, w*x1, w*x2, sum w)
__device__ __align__(16) float4 g_accf[MAXN];
__device__ __align__(16) float4 g_accr[MAXN];

// Layer-2: per-node state is (h2f, h2r); scores are h2 * uniform attention scalar.
__device__ __align__(8) float2 g_H[MAXN];
__device__ __align__(8) float2 g_nd2f[MAXN];
__device__ __align__(8) float2 g_nd2r[MAXN];

// ---------------- layer 1 node prep ----------------
__global__ void k_node1(const float* __restrict__ x,
                        const float* __restrict__ W1,  const float* __restrict__ as1,
                        const float* __restrict__ ad1,
                        const float* __restrict__ W1r, const float* __restrict__ as1r,
                        const float* __restrict__ ad1r, int N) {
    // one thread computes the uniform score-coefficient vectors for edge1
    if (blockIdx.x == 0 && threadIdx.x == 0) {
        float csf[3] = {0,0,0}, cdf[3] = {0,0,0}, csr[3] = {0,0,0}, cdr[3] = {0,0,0};
        for (int f = 0; f < 16; f++) {
            for (int k = 0; k < 3; k++) {
                float w  = W1[16 * k + f];
                float wr = W1r[16 * k + f];
                csf[k] += w * as1[f];  cdf[k] += w * ad1[f];
                csr[k] += wr * as1r[f]; cdr[k] += wr * ad1r[f];
            }
        }
        g_csf = make_float4(csf[0], csf[1], csf[2], 0.f);
        g_cdf = make_float4(cdf[0], cdf[1], cdf[2], 0.f);
        g_csr = make_float4(csr[0], csr[1], csr[2], 0.f);
        g_cdr = make_float4(cdr[0], cdr[1], cdr[2], 0.f);
    }

    int i = blockIdx.x * blockDim.x + threadIdx.x;
    if (i >= N) return;
    float x0 = x[3 * i], x1 = x[3 * i + 1], x2 = x[3 * i + 2];

    float csf[3] = {0.f, 0.f, 0.f}, cdf[3] = {0.f, 0.f, 0.f};
    float csr[3] = {0.f, 0.f, 0.f}, cdr[3] = {0.f, 0.f, 0.f};
#pragma unroll
    for (int f = 0; f < 16; f++) {
        float a1 = __ldg(&as1[f]),  a2 = __ldg(&ad1[f]);
        float a3 = __ldg(&as1r[f]), a4 = __ldg(&ad1r[f]);
#pragma unroll
        for (int k = 0; k < 3; k++) {
            float w  = __ldg(&W1[16 * k + f]);
            float wr = __ldg(&W1r[16 * k + f]);
            csf[k] += w * a1;  cdf[k] += w * a2;
            csr[k] += wr * a3; cdr[k] += wr * a4;
        }
    }
    float ssf = x0 * csf[0] + x1 * csf[1] + x2 * csf[2];
    float sdf = x0 * cdf[0] + x1 * cdf[1] + x2 * cdf[2];
    float ssr = x0 * csr[0] + x1 * csr[1] + x2 * csr[2];
    float sdr = x0 * cdr[0] + x1 * cdr[1] + x2 * cdr[2];

    g_X[i] = make_float4(x0, x1, x2, 0.f);

    // self-loop contribution
    float wf = __expf(lrelu(ssf + sdf));
    float wr = __expf(lrelu(ssr + sdr));
    g_accf[i] = make_float4(wf * x0, wf * x1, wf * x2, wf);
    g_accr[i] = make_float4(wr * x0, wr * x1, wr * x2, wr);
}

// ---------------- layer 1 edge pass: 2 gathers + 2 REDs per edge ----------------
__global__ void __launch_bounds__(256) k_edge1(const void* __restrict__ ei, int E) {
    // per-block int64-vs-int32 detection: odd 32-bit words of int64 data are
    // all-zero high halves; genuine int32 node ids are ~never 128-in-a-row zero.
    __shared__ int s_is64;
    if (threadIdx.x == 0) s_is64 = 1;
    __syncthreads();
    if (threadIdx.x < 128) {
        if (((const int*)ei)[1 + 2 * threadIdx.x] != 0) s_is64 = 0;
    }
    __syncthreads();
    bool is64 = (s_is64 != 0);

    int t = blockIdx.x * blockDim.x + threadIdx.x;
    int j0 = t * EPT;
    if (j0 >= E) return;
    int n = E - j0; if (n > EPT) n = EPT;

    float4 csf = g_csf, cdf = g_cdf, csr = g_csr, cdr = g_cdr;

    int s[EPT], d[EPT];
    if (is64) {
        const long long* p = (const long long*)ei;
#pragma unroll
        for (int u = 0; u < EPT; u++) if (u < n) { s[u] = (int)p[j0 + u]; d[u] = (int)p[E + j0 + u]; }
    } else {
        const int* p = (const int*)ei;
#pragma unroll
        for (int u = 0; u < EPT; u++) if (u < n) { s[u] = p[j0 + u]; d[u] = p[E + j0 + u]; }
    }
#pragma unroll
    for (int u = 0; u < EPT; u++) if (u < n) g_sd[j0 + u] = make_int2(s[u], d[u]);

    float4 Xs[EPT], Xd[EPT];
#pragma unroll
    for (int u = 0; u < EPT; u++) if (u < n) {
        Xs[u] = g_X[s[u]];
        Xd[u] = g_X[d[u]];
    }
#pragma unroll
    for (int u = 0; u < EPT; u++) if (u < n) {
        // forward edge s->d: exp(lrelu(ssf[s] + sdf[d])) -> accf[d]
        float wf = __expf(lrelu(dot3(Xs[u], csf) + dot3(Xd[u], cdf)));
        // reverse edge d->s: exp(lrelu(ssr[d] + sdr[s])) -> accr[s]
        float wr = __expf(lrelu(dot3(Xd[u], csr) + dot3(Xs[u], cdr)));
        red_add_v4((float*)&g_accf[d[u]], wf * Xs[u].x, wf * Xs[u].y, wf * Xs[u].z, wf);
        red_add_v4((float*)&g_accr[s[u]], wr * Xd[u].x, wr * Xd[u].y, wr * Xd[u].z, wr);
    }
}

// ---------------- layer 2 node prep ----------------
__global__ void k_node2(const float* __restrict__ W1, const float* __restrict__ b1,
                        const float* __restrict__ W2,
                        const float* __restrict__ as2, const float* __restrict__ ad2,
                        const float* __restrict__ W1r, const float* __restrict__ b1r,
                        const float* __restrict__ W2r,
                        const float* __restrict__ as2r, const float* __restrict__ ad2r, int N) {
    int i = blockIdx.x * blockDim.x + threadIdx.x;
    if (i >= N) return;
    float4 af = g_accf[i];
    float4 ar = g_accr[i];
    float invf = 1.f / (af.w + 1e-16f);
    float invr = 1.f / (ar.w + 1e-16f);
    float n0f = af.x * invf, n1f = af.y * invf, n2f = af.z * invf;
    float n0r = ar.x * invr, n1r = ar.y * invr, n2r = ar.z * invr;

    float h2f = 0.f, h2r = 0.f;
#pragma unroll
    for (int f = 0; f < 16; f++) {
        float vf = n0f * __ldg(&W1[f]) + n1f * __ldg(&W1[16 + f]) + n2f * __ldg(&W1[32 + f])
                 + __ldg(&b1[f]);
        float vr = n0r * __ldg(&W1r[f]) + n1r * __ldg(&W1r[16 + f]) + n2r * __ldg(&W1r[32 + f])
                 + __ldg(&b1r[f]);
        h2f += fmaxf(vf, 0.f) * __ldg(&W2[f]);
        h2r += fmaxf(vr, 0.f) * __ldg(&W2r[f]);
    }
    g_H[i] = make_float2(h2f, h2r);

    // self-loop contribution
    float wf = __expf(lrelu(h2f * (__ldg(&as2[0]) + __ldg(&ad2[0]))));
    float wr = __expf(lrelu(h2r * (__ldg(&as2r[0]) + __ldg(&ad2r[0]))));
    g_nd2f[i] = make_float2(wf * h2f, wf);
    g_nd2r[i] = make_float2(wr * h2r, wr);
}

// ---------------- layer 2 edge pass: 2 gathers + 2 REDs per edge ----------------
__global__ void __launch_bounds__(256) k_edge2(const float* __restrict__ as2,
                                               const float* __restrict__ ad2,
                                               const float* __restrict__ as2r,
                                               const float* __restrict__ ad2r, int E) {
    float a2s = __ldg(&as2[0]),  a2d = __ldg(&ad2[0]);
    float a2sr = __ldg(&as2r[0]), a2dr = __ldg(&ad2r[0]);

    int t = blockIdx.x * blockDim.x + threadIdx.x;
    int j0 = t * EPT;
    if (j0 >= E) return;
    int n = E - j0; if (n > EPT) n = EPT;

    int2 sd[EPT];
#pragma unroll
    for (int u = 0; u < EPT; u++) if (u < n) sd[u] = g_sd[j0 + u];

    float2 Hs[EPT], Hd[EPT];
#pragma unroll
    for (int u = 0; u < EPT; u++) if (u < n) {
        Hs[u] = g_H[sd[u].x];
        Hd[u] = g_H[sd[u].y];
    }
#pragma unroll
    for (int u = 0; u < EPT; u++) if (u < n) {
        // forward s->d: score = s2af[s] + s2bf[d] = h2f[s]*as2 + h2f[d]*ad2
        float wf = __expf(lrelu(Hs[u].x * a2s + Hd[u].x * a2d));
        // reverse d->s: score = s2ar[d] + s2br[s] = h2r[d]*as2r + h2r[s]*ad2r
        float wr = __expf(lrelu(Hd[u].y * a2sr + Hs[u].y * a2dr));
        red_add_v2((float*)&g_nd2f[sd[u].y], wf * Hs[u].x, wf);
        red_add_v2((float*)&g_nd2r[sd[u].x], wr * Hd[u].y, wr);
    }
}

// ---------------- final combine ----------------
__global__ void k_out(float* __restrict__ out, const float* __restrict__ b2,
                      const float* __restrict__ b2r, int N) {
    int i = blockIdx.x * blockDim.x + threadIdx.x;
    if (i >= N) return;
    float2 f = g_nd2f[i];
    float2 r = g_nd2r[i];
    float of  = f.x / (f.y + 1e-16f) + __ldg(&b2[0]);
    float orv = r.x / (r.y + 1e-16f) + __ldg(&b2r[0]);
    out[i] = 0.5f * (of + orv);
}

extern "C" void kernel_launch(void* const* d_in, const int* in_sizes, int n_in,
                              void* d_out, int out_size) {
    const float* x   = (const float*)d_in[0];
    const void*  ei  = d_in[1];
    const float* W1  = (const float*)d_in[2];
    const float* as1 = (const float*)d_in[3];
    const float* ad1 = (const float*)d_in[4];
    const float* b1  = (const float*)d_in[5];
    const float* W2  = (const float*)d_in[6];
    const float* as2 = (const float*)d_in[7];
    const float* ad2 = (const float*)d_in[8];
    const float* b2  = (const float*)d_in[9];
    const float* W1r  = (const float*)d_in[10];
    const float* as1r = (const float*)d_in[11];
    const float* ad1r = (const float*)d_in[12];
    const float* b1r  = (const float*)d_in[13];
    const float* W2r  = (const float*)d_in[14];
    const float* as2r = (const float*)d_in[15];
    const float* ad2r = (const float*)d_in[16];
    const float* b2r  = (const float*)d_in[17];

    int N = in_sizes[0] / 3;
    int E = in_sizes[1] / 2;

    const int TB = 256;
    int nbN = (N + TB - 1) / TB;
    int nbE = (E + TB * EPT - 1) / (TB * EPT);

    k_node1<<<nbN, TB>>>(x, W1, as1, ad1, W1r, as1r, ad1r, N);
    k_edge1<<<nbE, TB>>>(ei, E);
    k_node2<<<nbN, TB>>>(W1, b1, W2, as2, ad2, W1r, b1r, W2r, as2r, ad2r, N);
    k_edge2<<<nbE, TB>>>(as2, ad2, as2r, ad2r, E);
    k_out<<<nbN, TB>>>((float*)d_out, b2, b2r, N);
}

// round 5
// speedup vs baseline: 3.2154x; 1.0901x over previous
#include <cuda_runtime.h>

#define NEG_SLOPE 0.2f
#define MAXN 100000
#define MAXE 3200000
#define EPT 2          // edges per thread in edge passes

static __device__ __forceinline__ float lrelu(float v) {
    return v > 0.f ? v : NEG_SLOPE * v;
}

static __device__ __forceinline__ void red_add_v2(float* addr, float a, float b) {
    asm volatile("red.global.add.v2.f32 [%0], {%1,%2};" :: "l"(addr), "f"(a), "f"(b) : "memory");
}
static __device__ __forceinline__ void red_add_v4(float* addr, float a, float b, float c, float d) {
    asm volatile("red.global.add.v4.f32 [%0], {%1,%2,%3,%4};"
                 :: "l"(addr), "f"(a), "f"(b), "f"(c), "f"(d) : "memory");
}

static __device__ __forceinline__ float dot3(float4 v, float4 c) {
    return v.x * c.x + v.y * c.y + v.z * c.z;
}

// ---------------- scratch (device globals; no runtime allocation) ----------------
__device__ __align__(16) int2 g_sd[MAXE];    // packed (src,dst): written by edge1, read by edge2

// Layer-1: per-node state is x (float4, 1 sector). Scores are linear in x.
__device__ __align__(16) float4 g_X[MAXN];
__device__ float4 g_csf, g_cdf, g_csr, g_cdr;   // W1@as1, W1@ad1, W1r@as1r, W1r@ad1r
// Accumulators: (sum w*x0, w*x1, w*x2, sum w)
__device__ __align__(16) float4 g_accf[MAXN];
__device__ __align__(16) float4 g_accr[MAXN];

// Layer-2: per-node state is (h2f, h2r).
__device__ __align__(16) float2 g_H[MAXN];
__device__ __align__(16) float2 g_nd2f[MAXN];
__device__ __align__(16) float2 g_nd2r[MAXN];

// ---------------- uniform score coefficients (once) ----------------
__global__ void k_coef(const float* __restrict__ W1,  const float* __restrict__ as1,
                       const float* __restrict__ ad1,
                       const float* __restrict__ W1r, const float* __restrict__ as1r,
                       const float* __restrict__ ad1r) {
    if (threadIdx.x != 0) return;
    float csf[3] = {0,0,0}, cdf[3] = {0,0,0}, csr[3] = {0,0,0}, cdr[3] = {0,0,0};
    for (int f = 0; f < 16; f++) {
        for (int k = 0; k < 3; k++) {
            float w  = W1[16 * k + f];
            float wr = W1r[16 * k + f];
            csf[k] += w * as1[f];   cdf[k] += w * ad1[f];
            csr[k] += wr * as1r[f]; cdr[k] += wr * ad1r[f];
        }
    }
    g_csf = make_float4(csf[0], csf[1], csf[2], 0.f);
    g_cdf = make_float4(cdf[0], cdf[1], cdf[2], 0.f);
    g_csr = make_float4(csr[0], csr[1], csr[2], 0.f);
    g_cdr = make_float4(cdr[0], cdr[1], cdr[2], 0.f);
}

// ---------------- layer 1 node prep ----------------
__global__ void k_node1(const float* __restrict__ x, int N) {
    int i = blockIdx.x * blockDim.x + threadIdx.x;
    if (i >= N) return;
    float4 csf = g_csf, cdf = g_cdf, csr = g_csr, cdr = g_cdr;
    float x0 = x[3 * i], x1 = x[3 * i + 1], x2 = x[3 * i + 2];
    float4 X = make_float4(x0, x1, x2, 0.f);

    float ssf = dot3(X, csf), sdf = dot3(X, cdf);
    float ssr = dot3(X, csr), sdr = dot3(X, cdr);

    g_X[i] = X;
    // self-loop contribution
    float wf = __expf(lrelu(ssf + sdf));
    float wr = __expf(lrelu(ssr + sdr));
    g_accf[i] = make_float4(wf * x0, wf * x1, wf * x2, wf);
    g_accr[i] = make_float4(wr * x0, wr * x1, wr * x2, wr);
}

// ---------------- layer 1 edge pass: 2 gathers + 2 REDs per edge ----------------
__global__ void __launch_bounds__(256) k_edge1(const void* __restrict__ ei, int E) {
    // per-block int64-vs-int32 detection: odd 32-bit words of int64 data are
    // all-zero high halves; genuine int32 node ids are ~never 128-in-a-row zero.
    __shared__ int s_is64;
    if (threadIdx.x == 0) s_is64 = 1;
    __syncthreads();
    if (threadIdx.x < 128) {
        if (((const int*)ei)[1 + 2 * threadIdx.x] != 0) s_is64 = 0;
    }
    __syncthreads();
    bool is64 = (s_is64 != 0);

    int t = blockIdx.x * blockDim.x + threadIdx.x;
    int j0 = t * EPT;
    if (j0 >= E) return;
    int n = E - j0; if (n > EPT) n = EPT;

    float4 csf = g_csf, cdf = g_cdf, csr = g_csr, cdr = g_cdr;

    int s[EPT], d[EPT];
    if (is64) {
        const long long* p = (const long long*)ei;
#pragma unroll
        for (int u = 0; u < EPT; u++) if (u < n) { s[u] = (int)p[j0 + u]; d[u] = (int)p[E + j0 + u]; }
    } else {
        const int* p = (const int*)ei;
#pragma unroll
        for (int u = 0; u < EPT; u++) if (u < n) { s[u] = p[j0 + u]; d[u] = p[E + j0 + u]; }
    }
#pragma unroll
    for (int u = 0; u < EPT; u++) if (u < n) g_sd[j0 + u] = make_int2(s[u], d[u]);

    float4 Xs[EPT], Xd[EPT];
#pragma unroll
    for (int u = 0; u < EPT; u++) if (u < n) {
        Xs[u] = g_X[s[u]];
        Xd[u] = g_X[d[u]];
    }
#pragma unroll
    for (int u = 0; u < EPT; u++) if (u < n) {
        // forward edge s->d: exp(lrelu(ssf[s] + sdf[d])) -> accf[d]
        float wf = __expf(lrelu(dot3(Xs[u], csf) + dot3(Xd[u], cdf)));
        // reverse edge d->s: exp(lrelu(ssr[d] + sdr[s])) -> accr[s]
        float wr = __expf(lrelu(dot3(Xd[u], csr) + dot3(Xs[u], cdr)));
        red_add_v4((float*)&g_accf[d[u]], wf * Xs[u].x, wf * Xs[u].y, wf * Xs[u].z, wf);
        red_add_v4((float*)&g_accr[s[u]], wr * Xd[u].x, wr * Xd[u].y, wr * Xd[u].z, wr);
    }
}

// ---------------- layer 2 node prep (vectorized weight loads) ----------------
__global__ void k_node2(const float* __restrict__ W1, const float* __restrict__ b1,
                        const float* __restrict__ W2,
                        const float* __restrict__ as2, const float* __restrict__ ad2,
                        const float* __restrict__ W1r, const float* __restrict__ b1r,
                        const float* __restrict__ W2r,
                        const float* __restrict__ as2r, const float* __restrict__ ad2r, int N) {
    int i = blockIdx.x * blockDim.x + threadIdx.x;
    if (i >= N) return;
    float4 af = g_accf[i];
    float4 ar = g_accr[i];
    float invf = 1.f / (af.w + 1e-16f);
    float invr = 1.f / (ar.w + 1e-16f);
    float n0f = af.x * invf, n1f = af.y * invf, n2f = af.z * invf;
    float n0r = ar.x * invr, n1r = ar.y * invr, n2r = ar.z * invr;

    const float4* W1v  = (const float4*)W1;   // [3][4] float4s
    const float4* W1rv = (const float4*)W1r;
    const float4* b1v  = (const float4*)b1;
    const float4* b1rv = (const float4*)b1r;
    const float4* W2v  = (const float4*)W2;
    const float4* W2rv = (const float4*)W2r;

    float h2f = 0.f, h2r = 0.f;
#pragma unroll
    for (int q = 0; q < 4; q++) {
        float4 w0 = __ldg(&W1v[q]),     w1 = __ldg(&W1v[4 + q]),  w2 = __ldg(&W1v[8 + q]);
        float4 bb = __ldg(&b1v[q]),     wo = __ldg(&W2v[q]);
        float4 r0 = __ldg(&W1rv[q]),    r1 = __ldg(&W1rv[4 + q]), r2 = __ldg(&W1rv[8 + q]);
        float4 br = __ldg(&b1rv[q]),    ro = __ldg(&W2rv[q]);

        h2f += fmaxf(n0f * w0.x + n1f * w1.x + n2f * w2.x + bb.x, 0.f) * wo.x;
        h2f += fmaxf(n0f * w0.y + n1f * w1.y + n2f * w2.y + bb.y, 0.f) * wo.y;
        h2f += fmaxf(n0f * w0.z + n1f * w1.z + n2f * w2.z + bb.z, 0.f) * wo.z;
        h2f += fmaxf(n0f * w0.w + n1f * w1.w + n2f * w2.w + bb.w, 0.f) * wo.w;

        h2r += fmaxf(n0r * r0.x + n1r * r1.x + n2r * r2.x + br.x, 0.f) * ro.x;
        h2r += fmaxf(n0r * r0.y + n1r * r1.y + n2r * r2.y + br.y, 0.f) * ro.y;
        h2r += fmaxf(n0r * r0.z + n1r * r1.z + n2r * r2.z + br.z, 0.f) * ro.z;
        h2r += fmaxf(n0r * r0.w + n1r * r1.w + n2r * r2.w + br.w, 0.f) * ro.w;
    }
    g_H[i] = make_float2(h2f, h2r);

    // self-loop contribution
    float wf = __expf(lrelu(h2f * (__ldg(&as2[0]) + __ldg(&ad2[0]))));
    float wr = __expf(lrelu(h2r * (__ldg(&as2r[0]) + __ldg(&ad2r[0]))));
    g_nd2f[i] = make_float2(wf * h2f, wf);
    g_nd2r[i] = make_float2(wr * h2r, wr);
}

// ---------------- layer 2 edge pass: 2 gathers + 2 REDs per edge ----------------
__global__ void __launch_bounds__(256) k_edge2(const float* __restrict__ as2,
                                               const float* __restrict__ ad2,
                                               const float* __restrict__ as2r,
                                               const float* __restrict__ ad2r, int E) {
    float a2s = __ldg(&as2[0]),  a2d = __ldg(&ad2[0]);
    float a2sr = __ldg(&as2r[0]), a2dr = __ldg(&ad2r[0]);

    int t = blockIdx.x * blockDim.x + threadIdx.x;
    int j0 = t * EPT;
    if (j0 >= E) return;
    int n = E - j0; if (n > EPT) n = EPT;

    int2 sd[EPT];
#pragma unroll
    for (int u = 0; u < EPT; u++) if (u < n) sd[u] = g_sd[j0 + u];

    float2 Hs[EPT], Hd[EPT];
#pragma unroll
    for (int u = 0; u < EPT; u++) if (u < n) {
        Hs[u] = g_H[sd[u].x];
        Hd[u] = g_H[sd[u].y];
    }
#pragma unroll
    for (int u = 0; u < EPT; u++) if (u < n) {
        // forward s->d: score = h2f[s]*as2 + h2f[d]*ad2
        float wf = __expf(lrelu(Hs[u].x * a2s + Hd[u].x * a2d));
        // reverse d->s: score = h2r[d]*as2r + h2r[s]*ad2r
        float wr = __expf(lrelu(Hd[u].y * a2sr + Hs[u].y * a2dr));
        red_add_v2((float*)&g_nd2f[sd[u].y], wf * Hs[u].x, wf);
        red_add_v2((float*)&g_nd2r[sd[u].x], wr * Hd[u].y, wr);
    }
}

// ---------------- final combine (2 nodes/thread, vectorized) ----------------
__global__ void k_out(float* __restrict__ out, const float* __restrict__ b2,
                      const float* __restrict__ b2r, int N) {
    int t = blockIdx.x * blockDim.x + threadIdx.x;
    int i = 2 * t;
    if (i >= N) return;
    float bf = __ldg(&b2[0]), br = __ldg(&b2r[0]);
    float4 f = ((const float4*)g_nd2f)[t];   // nd2f[i], nd2f[i+1]
    float4 r = ((const float4*)g_nd2r)[t];
    float o0 = 0.5f * (f.x / (f.y + 1e-16f) + bf + r.x / (r.y + 1e-16f) + br);
    if (i + 1 < N) {
        float o1 = 0.5f * (f.z / (f.w + 1e-16f) + bf + r.z / (r.w + 1e-16f) + br);
        *(float2*)&out[i] = make_float2(o0, o1);
    } else {
        out[i] = o0;
    }
}

extern "C" void kernel_launch(void* const* d_in, const int* in_sizes, int n_in,
                              void* d_out, int out_size) {
    const float* x   = (const float*)d_in[0];
    const void*  ei  = d_in[1];
    const float* W1  = (const float*)d_in[2];
    const float* as1 = (const float*)d_in[3];
    const float* ad1 = (const float*)d_in[4];
    const float* b1  = (const float*)d_in[5];
    const float* W2  = (const float*)d_in[6];
    const float* as2 = (const float*)d_in[7];
    const float* ad2 = (const float*)d_in[8];
    const float* b2  = (const float*)d_in[9];
    const float* W1r  = (const float*)d_in[10];
    const float* as1r = (const float*)d_in[11];
    const float* ad1r = (const float*)d_in[12];
    const float* b1r  = (const float*)d_in[13];
    const float* W2r  = (const float*)d_in[14];
    const float* as2r = (const float*)d_in[15];
    const float* ad2r = (const float*)d_in[16];
    const float* b2r  = (const float*)d_in[17];

    int N = in_sizes[0] / 3;
    int E = in_sizes[1] / 2;

    const int TB = 256;
    int nbN = (N + TB - 1) / TB;
    int nbE = (E + TB * EPT - 1) / (TB * EPT);
    int nbO = (N + TB * 2 - 1) / (TB * 2);

    k_coef<<<1, 32>>>(W1, as1, ad1, W1r, as1r, ad1r);
    k_node1<<<nbN, TB>>>(x, N);
    k_edge1<<<nbE, TB>>>(ei, E);
    k_node2<<<nbN, TB>>>(W1, b1, W2, as2, ad2, W1r, b1r, W2r, as2r, ad2r, N);
    k_edge2<<<nbE, TB>>>(as2, ad2, as2r, ad2r, E);
    k_out<<<nbO, TB>>>((float*)d_out, b2, b2r, N);
}